// round 16
// baseline (speedup 1.0000x reference)
#include <cuda_runtime.h>
#include <cuda_fp16.h>

typedef unsigned int u32;

#define ATOT 150111
#define NB   4

// ---------------- static device scratch ----------------
static __device__ __align__(128) __half g_x[52859904];    // padded NHWC fp16 features (825936 rows x 64)
static __device__ __align__(128) __half g_wb[36*512*64];  // conv weights per k-block
static __device__ __align__(128) float  g_part[4*204288*20]; // head partials per n-slice (stride 20)

#define PSLICE 4085760u   // 204288*20 floats per n-slice

__constant__ int c_H[5]     = {150,75,38,19,10};
__constant__ int c_W[5]     = {250,125,63,32,16};
__constant__ int c_Wp[5]    = {252,127,65,34,18};
__constant__ int c_Hp[5]    = {152,77,40,21,12};
__constant__ int c_plane[5] = {38304,9779,2600,714,216};
__constant__ int c_xbase[5] = {0,612864,769328,810928,822352};
__constant__ int c_sEnd[5]  = {296,371,391,397,399};   // strip cum-ends per b
__constant__ int c_rowBase[5] = {0,112500,140625,147807,149631};
// prep_x block decode
__constant__ int c_pbEnd[5] = {19200,24000,25216,25520,25680};
__constant__ int c_wbl[5]   = {8,4,2,1,1};
// zero_pad decode: border rows per level (cum) and per-plane counts
__constant__ int c_bEnd[5]  = {12864,19328,22624,24320,25216};
__constant__ int c_bpp[5]   = {804,404,206,106,56};

#define NTILE 1596   // 4 b * 399 strips

// merged prep grid layout
#define PB_X   25680                 // prep_x blocks
#define PB_Z   792                   // zero_pad blocks (25344*8/256)
#define PB_W   512                   // prep_w blocks (1 o-channel each, smem transpose)
#define PB_ALL (PB_X + PB_Z + PB_W)

__device__ __forceinline__ u32 smem_u32(const void* p){
    u32 a; asm("{ .reg .u64 t; cvta.to.shared.u64 t, %1; cvt.u32.u64 %0, t; }":"=r"(a):"l"(p));
    return a;
}
#define CP_ASYNC16(dst,src) asm volatile("cp.async.cg.shared.global [%0], [%1], 16;"::"r"(dst),"l"(src):"memory")
#define CP_COMMIT()     asm volatile("cp.async.commit_group;":::"memory")
#define CP_WAIT(n)      asm volatile("cp.async.wait_group %0;"::"n"(n):"memory")
#define LDSM_X4(r0,r1,r2,r3,a) asm volatile("ldmatrix.sync.aligned.m8n8.x4.shared.b16 {%0,%1,%2,%3}, [%4];" \
    : "=r"(r0),"=r"(r1),"=r"(r2),"=r"(r3) : "r"(a))
#define MMA16816(c0,c1,c2,c3,a0,a1,a2,a3,b0,b1) \
    asm volatile("mma.sync.aligned.m16n8k16.row.col.f32.f16.f16.f32 {%0,%1,%2,%3},{%4,%5,%6,%7},{%8,%9},{%0,%1,%2,%3};" \
    : "+f"(c0),"+f"(c1),"+f"(c2),"+f"(c3) : "r"(a0),"r"(a1),"r"(a2),"r"(a3),"r"(b0),"r"(b1))

// ---------------- merged prep kernel ----------------
__global__ __launch_bounds__(256)
void prep(const float* p0,const float* p1,const float* p2,const float* p3,const float* p4,
          const float* __restrict__ Wc)
{
    __shared__ __align__(16) char sbuf[4608];
    const int tid = threadIdx.x;
    int bid = blockIdx.x;

    if (bid < PB_X) {
        // ---- prep_x: NCHW fp32 -> padded NHWC fp16 (interior rows) ----
        __half (*s)[72] = (__half(*)[72])sbuf;   // 144B row stride: conflict-free 128-bit ops
        int l = 0;
        while (bid >= c_pbEnd[l]) l++;
        int r = bid - (l ? c_pbEnd[l-1] : 0);
        int H = c_H[l], W = c_W[l], Wp = c_Wp[l], plane = c_plane[l];
        int wbl = c_wbl[l];
        int wb = r % wbl; int t1 = r / wbl;
        int h = t1 % H;   int bc = t1 / H;
        int b = bc >> 2, cc = bc & 3;
        const float* x = (l==0)?p0:(l==1)?p1:(l==2)?p2:(l==3)?p3:p4;

        {
            // thread handles 8 CONSECUTIVE channels (warp-uniform channel per iter -> coalesced)
            int c0 = tid >> 5, wl = tid & 31;
            int w = wb*32 + wl;
            const float* px = x + ((size_t)(b*256 + cc*64 + c0*8)*H + h)*W + w;
            size_t cs = (size_t)H*W;
            __half2 hv[4];
#pragma unroll
            for (int i = 0; i < 4; i++) {
                float v0 = (w < W) ? __ldcs(px + (2*i)*cs)   : 0.f;
                float v1 = (w < W) ? __ldcs(px + (2*i+1)*cs) : 0.f;
                hv[i] = __floats2half2_rn(v0, v1);
            }
            *(uint4*)&s[wl][c0*8] = *(uint4*)hv;       // single STS.128
        }
        __syncthreads();
        {
            int cu = tid & 7, wl = tid >> 3;
            int w = wb*32 + wl;
            if (w < W) {
                size_t row = (size_t)c_xbase[l] + (size_t)(b*4 + cc)*plane + (size_t)(h+1)*Wp + (w+1);
                uint4 v = *(uint4*)&s[wl][cu*8];       // single LDS.128
                __stcs((uint4*)((char*)g_x + row*128 + cu*16), v);
            }
        }
        return;
    }
    bid -= PB_X;

    if (bid < PB_Z) {
        // ---- zero border rows + trailing slack ----
        int id = bid*256 + tid;
        if (id >= 25344*8) return;
        int bi = id >> 3, u = id & 7;
        size_t row;
        if (bi >= 25216) {
            row = 825808 + (bi - 25216);
        } else {
            int l = 0; while (bi >= c_bEnd[l]) l++;
            int r = bi - (l ? c_bEnd[l-1] : 0);
            int k = c_bpp[l];
            int plane = r / k, j = r - plane*k;
            int Wp = c_Wp[l], Hp = c_Hp[l], W = c_W[l];
            int hp, wp;
            if (j < 2*Wp) { hp = (j >= Wp) ? (Hp-1) : 0; wp = (j >= Wp) ? (j - Wp) : j; }
            else { int j2 = j - 2*Wp; hp = 1 + (j2 >> 1); wp = (j2 & 1) ? (W+1) : 0; }
            row = (size_t)c_xbase[l] + (size_t)plane*c_plane[l] + (size_t)hp*Wp + wp;
        }
        __stcs((uint4*)((char*)g_x + row*128 + u*16), make_uint4(0,0,0,0));
        return;
    }
    bid -= PB_Z;

    // ---- prep_w: smem transpose, 1 o-channel per block ----
    {
        __half* sh = (__half*)sbuf;                  // [2304] halfs = 4608 B
        int o = bid;
        for (int i = tid; i < 2304; i += 256)
            sh[i] = __float2half_rn(Wc[(size_t)o*2304 + i]);
        __syncthreads();
        for (int u = tid; u < 288; u += 256) {
            int kb = u >> 3, jq = u & 7;
            int cc = kb & 3, t = kb >> 2;
            __half hv[8];
#pragma unroll
            for (int j = 0; j < 8; j++)
                hv[j] = sh[(cc*64 + jq*8 + j)*9 + t];
            *(uint4*)&g_wb[(size_t)kb*32768 + (size_t)o*64 + jq*8] = *(uint4*)hv;
        }
    }
}

// ---------------- gemm1: conv as implicit GEMM (HMMA) + fused head ----------------
#define STG_STRIDE 32768
#define SMEM_G1    (98304 + 6528)   // 3 stages + W_head [24][136] fp16

__global__ void __launch_bounds__(256, 2)
gemm1(const float* __restrict__ b_conv,
      const float* __restrict__ W_cls, const float* __restrict__ W_box)
{
    extern __shared__ char sm[];
    const u32 sb = smem_u32(sm);
    const int tid = threadIdx.x, lane = tid & 31, warp = tid >> 5;
    const int wm = warp & 1, wn = warp >> 1;
    const int n0 = blockIdx.x << 7;
    const int tile = blockIdx.y;

    // strip decode
    int b = tile / 399; int r = tile - b*399;
    int l = 0; while (r >= c_sEnd[l]) l++;
    int s = r - (l ? c_sEnd[l-1] : 0);
    int Wp = c_Wp[l], plane = c_plane[l];
    size_t abase = (size_t)c_xbase[l] + (size_t)(b*4)*plane + (size_t)s*128;

    u32 dsw[4];
#pragma unroll
    for (int q = 0; q < 4; q++) {
        int u = tid + q*256, row = u >> 3, col = u & 7;
        dsw[q] = row*128 + (col ^ (row & 7))*16;
    }

    float c[4][4][4];
#pragma unroll
    for (int mf=0; mf<4; mf++)
#pragma unroll
        for (int nf=0; nf<4; nf++)
#pragma unroll
            for (int q=0; q<4; q++) c[mf][nf][q] = 0.f;

#define GA_PTR(KB) ((const char*)g_x + (abase + (size_t)((KB) & 3)*plane +            \
        (size_t)((((KB)>>2) >= 6) ? 2 : (((KB)>>2) >= 3) ? 1 : 0)*Wp +                \
        (size_t)(((KB)>>2) - ((((KB)>>2) >= 6) ? 2 : (((KB)>>2) >= 3) ? 1 : 0)*3))*128)
#define GB_PTR(KB) ((const char*)g_wb + ((size_t)(KB)*512 + n0)*128)

#define LOAD_A(KB, SLOT) do {                                                  \
        const char* _gA = GA_PTR(KB);                                          \
        u32 _s = sb + (SLOT)*STG_STRIDE;                                       \
        _Pragma("unroll")                                                      \
        for (int _r = 0; _r < 4; _r++)                                         \
            CP_ASYNC16(_s + dsw[_r], _gA + tid*16 + _r*4096);                  \
    } while (0)
#define LOAD_B(KB, SLOT) do {                                                  \
        const char* _gB = GB_PTR(KB);                                          \
        u32 _s = sb + (SLOT)*STG_STRIDE + 16384;                               \
        _Pragma("unroll")                                                      \
        for (int _r = 0; _r < 4; _r++)                                         \
            CP_ASYNC16(_s + dsw[_r], _gB + tid*16 + _r*4096);                  \
    } while (0)

#define KS_STEP(ST, KS) do {                                                   \
        u32 a[4][4];                                                           \
        _Pragma("unroll")                                                      \
        for (int mf = 0; mf < 4; mf++)                                         \
            LDSM_X4(a[mf][0], a[mf][1], a[mf][2], a[mf][3],                    \
                    (ST) + mf*2048 + offA[KS]);                                \
        u32 bf[4][2];                                                          \
        _Pragma("unroll")                                                      \
        for (int pr = 0; pr < 2; pr++)                                         \
            LDSM_X4(bf[2*pr][0], bf[2*pr][1], bf[2*pr+1][0], bf[2*pr+1][1],    \
                    (ST) + pr*2048 + offB[KS]);                                \
        _Pragma("unroll")                                                      \
        for (int mf = 0; mf < 4; mf++)                                         \
            _Pragma("unroll")                                                  \
            for (int nf = 0; nf < 4; nf++)                                     \
                MMA16816(c[mf][nf][0], c[mf][nf][1], c[mf][nf][2], c[mf][nf][3],\
                         a[mf][0], a[mf][1], a[mf][2], a[mf][3],               \
                         bf[nf][0], bf[nf][1]);                                \
    } while (0)

    // prologue loads FIRST so sWh staging overlaps the DRAM latency
    LOAD_A(0, 0); LOAD_B(0, 0); CP_COMMIT();
    LOAD_A(1, 1); LOAD_B(1, 1); CP_COMMIT();

    // stage head-weight slice: sWh[24][136] fp16 (rows 18..23 zero)
    {
        __half* sWh = (__half*)(sm + 98304);
        for (int i = tid; i < 24*128; i += 256) {
            int j = i >> 7, k = i & 127;
            float v = (j < 6) ? W_cls[j*512 + n0 + k]
                    : (j < 18) ? W_box[(j-6)*512 + n0 + k] : 0.f;
            sWh[j*136 + k] = __float2half_rn(v);
        }
    }

    u32 offA[4], offB[4];
    {
        int rowA = wm*64 + (lane & 15), kA = lane >> 4;
        int rB0  = wn*32 + ((lane >> 4) << 3) + (lane & 7), kB = (lane >> 3) & 1;
#pragma unroll
        for (int ks = 0; ks < 4; ks++) {
            offA[ks] = rowA*128 + ((2*ks + kA) ^ (rowA & 7))*16;
            offB[ks] = rB0*128 + 16384 + ((2*ks + kB) ^ (lane & 7))*16;
        }
    }

    CP_WAIT(1);
    __syncthreads();

#pragma unroll 3
    for (int kb = 0; kb < 36; kb++) {
        const int slot = kb % 3;
        const int nslot = (kb + 2) % 3;
        u32 st = sb + slot*STG_STRIDE;

        KS_STEP(st, 0);
        if (kb + 2 < 36) LOAD_A(kb + 2, nslot);
        KS_STEP(st, 1);
        if (kb + 2 < 36) LOAD_B(kb + 2, nslot);
        CP_COMMIT();
        KS_STEP(st, 2);
        KS_STEP(st, 3);

        CP_WAIT(1);
        __syncthreads();
    }

    // ---- fused epilogue: bias + ReLU -> fp16 tile in smem (slot 0, swizzled) ----
#pragma unroll
    for (int nf = 0; nf < 4; nf++) {
        int chl = wn*32 + nf*8 + (lane & 3)*2;      // 0..127
        int half = chl >> 6, chin = chl & 63;
        float bx = b_conv[n0 + chl], by = b_conv[n0 + chl + 1];
#pragma unroll
        for (int mf = 0; mf < 4; mf++) {
            int pos = wm*64 + mf*16 + (lane >> 2);
            float v0 = c[mf][nf][0] + bx, v1 = c[mf][nf][1] + by;
            float v2 = c[mf][nf][2] + bx, v3 = c[mf][nf][3] + by;
            v0 = v0 > 0.f ? v0 : 0.f;  v1 = v1 > 0.f ? v1 : 0.f;
            v2 = v2 > 0.f ? v2 : 0.f;  v3 = v3 > 0.f ? v3 : 0.f;
            __half2 h01 = __floats2half2_rn(v0, v1);
            __half2 h23 = __floats2half2_rn(v2, v3);
            u32 a0 = (u32)((half*128 + pos)*128     + (((chin>>3) ^ (pos & 7)))*16     + (chin & 7)*2);
            u32 a1 = (u32)((half*128 + pos + 8)*128 + (((chin>>3) ^ ((pos+8) & 7)))*16 + (chin & 7)*2);
            *(u32*)(sm + a0) = *(u32*)&h01;
            *(u32*)(sm + a1) = *(u32*)&h23;
        }
    }
    __syncthreads();

    // ---- head projection: per warp M=16, N=24, K=128 ----
    float c2[3][4];
#pragma unroll
    for (int nf=0; nf<3; nf++)
#pragma unroll
        for (int q=0; q<4; q++) c2[nf][q] = 0.f;

    const char* sWb = sm + 98304;
    {
        int rowA = warp*16 + (lane & 15), kA = lane >> 4;
        int nIdx = lane >> 2, kLo = (lane & 3)*2;
#pragma unroll
        for (int half = 0; half < 2; half++)
#pragma unroll
            for (int ks = 0; ks < 4; ks++) {
                u32 a0,a1,a2,a3;
                LDSM_X4(a0,a1,a2,a3,
                        sb + (half*128 + rowA)*128 + ((2*ks + kA) ^ (rowA & 7))*16);
                int k0 = half*64 + ks*16 + kLo;
#pragma unroll
                for (int nf = 0; nf < 3; nf++) {
                    int n = nf*8 + nIdx;
                    u32 b0 = *(const u32*)(sWb + (n*136 + k0)*2);
                    u32 b1 = *(const u32*)(sWb + (n*136 + k0 + 8)*2);
                    MMA16816(c2[nf][0], c2[nf][1], c2[nf][2], c2[nf][3],
                             a0, a1, a2, a3, b0, b1);
                }
            }
    }

    // ---- store 18-dim partials for this n-slice (stride 20, streaming) ----
    {
        float* gp = g_part + (size_t)blockIdx.x*PSLICE + (size_t)tile*128*20;
        int pos0 = warp*16 + (lane >> 2);
        int ncol = (lane & 3)*2;
#pragma unroll
        for (int nf = 0; nf < 3; nf++) {
            int n = nf*8 + ncol;
            if (n < 18) {
                __stcs(&gp[pos0*20 + n],     c2[nf][0]);
                __stcs(&gp[(pos0+8)*20 + n], c2[nf][2]);
            }
            if (n + 1 < 18) {
                __stcs(&gp[pos0*20 + n + 1],     c2[nf][1]);
                __stcs(&gp[(pos0+8)*20 + n + 1], c2[nf][3]);
            }
        }
    }
}

// ---------------- scatter: sum 4 slices + bias + softmax + write (4 tiles/block) ----------------
__global__ __launch_bounds__(512)
void scatter(const float* __restrict__ b_cls, const float* __restrict__ b_box,
             float* __restrict__ out)
{
    const int tid = threadIdx.x & 127;
    const int tile = blockIdx.x*4 + (threadIdx.x >> 7);

    int b = tile / 399; int r = tile - b*399;
    int l = 0; while (r >= c_sEnd[l]) l++;
    int s = r - (l ? c_sEnd[l-1] : 0);
    int W = c_W[l], H = c_H[l], Wp = c_Wp[l];

    int q = Wp + 1 + s*128 + tid;
    int hp = q / Wp, wp = q - hp*Wp;
    if (wp >= 1 && wp <= W && hp <= H) {
        int h = hp - 1, w = wp - 1;
        size_t base = ((size_t)tile*128 + tid)*20;
        float so[20];
#pragma unroll
        for (int qq = 0; qq < 5; qq++) {
            float4 v0 = __ldcs((const float4*)&g_part[base + qq*4]);
            float4 v1 = __ldcs((const float4*)&g_part[PSLICE + base + qq*4]);
            float4 v2 = __ldcs((const float4*)&g_part[2u*PSLICE + base + qq*4]);
            float4 v3 = __ldcs((const float4*)&g_part[3u*PSLICE + base + qq*4]);
            so[qq*4+0] = v0.x + v1.x + v2.x + v3.x;
            so[qq*4+1] = v0.y + v1.y + v2.y + v3.y;
            so[qq*4+2] = v0.z + v1.z + v2.z + v3.z;
            so[qq*4+3] = v0.w + v1.w + v2.w + v3.w;
        }
#pragma unroll
        for (int j = 0; j < 18; j++)
            so[j] += (j < 6 ? b_cls[j] : b_box[j-6]);
        int rowo = c_rowBase[l] + (h*W + w)*3;
        float* pout = out + (size_t)2*NB*ATOT;
        float* bout = out + (size_t)4*NB*ATOT;
#pragma unroll
        for (int a = 0; a < 3; a++) {
            int row = rowo + a;
            int base2 = (b*ATOT + row)*2;
            __stcs(&out[base2],   so[2*a]);
            __stcs(&out[base2+1], so[2*a+1]);
#pragma unroll
            for (int k = 0; k < 2; k++) {
                int c2 = 2*a + k, rr = c2 % 3;
                float u0 = so[rr], v0 = so[rr+3];
                float m  = fmaxf(u0, v0);
                float eu = __expf(u0 - m), ev = __expf(v0 - m);
                __stcs(&pout[base2+k], ((c2 < 3) ? eu : ev) / (eu + ev));
            }
            int base4 = (b*ATOT + row)*4;
#pragma unroll
            for (int j = 0; j < 4; j++) __stcs(&bout[base4+j], so[6 + 4*a + j]);
        }
    }
}

extern "C" void kernel_launch(void* const* d_in, const int* in_sizes, int n_in,
                              void* d_out, int out_size) {
    const float* f[5]; for (int i = 0; i < 5; i++) f[i] = (const float*)d_in[i];
    const float* W_conv = (const float*)d_in[6];
    const float* b_conv = (const float*)d_in[7];
    const float* W_cls  = (const float*)d_in[8];
    const float* b_cls  = (const float*)d_in[9];
    const float* W_box  = (const float*)d_in[10];
    const float* b_box  = (const float*)d_in[11];
    float* out = (float*)d_out;

    cudaFuncSetAttribute(gemm1, cudaFuncAttributeMaxDynamicSharedMemorySize, SMEM_G1);

    prep<<<PB_ALL, 256>>>(f[0], f[1], f[2], f[3], f[4], W_conv);
    gemm1<<<dim3(4, NTILE), 256, SMEM_G1>>>(b_conv, W_cls, W_box);
    scatter<<<NTILE/4, 512>>>(b_cls, b_box, out);
}

// round 17
// speedup vs baseline: 1.0073x; 1.0073x over previous
#include <cuda_runtime.h>
#include <cuda_fp16.h>

typedef unsigned int u32;

#define ATOT 150111
#define NB   4

// ---------------- static device scratch ----------------
static __device__ __align__(128) __half g_x[52859904];    // padded NHWC fp16 features (825936 rows x 64)
static __device__ __align__(128) __half g_wb[36*512*64];  // conv weights per k-block
static __device__ __align__(128) float  g_part[4*204288*20]; // head partials per n-slice (stride 20)

#define PSLICE 4085760u   // 204288*20 floats per n-slice

__constant__ int c_H[5]     = {150,75,38,19,10};
__constant__ int c_W[5]     = {250,125,63,32,16};
__constant__ int c_Wp[5]    = {252,127,65,34,18};
__constant__ int c_Hp[5]    = {152,77,40,21,12};
__constant__ int c_plane[5] = {38304,9779,2600,714,216};
__constant__ int c_xbase[5] = {0,612864,769328,810928,822352};
__constant__ int c_sEnd[5]  = {296,371,391,397,399};   // strip cum-ends per b
__constant__ int c_rowBase[5] = {0,112500,140625,147807,149631};
// prep_x block decode
__constant__ int c_pbEnd[5] = {19200,24000,25216,25520,25680};
__constant__ int c_wbl[5]   = {8,4,2,1,1};
// zero_pad decode: border rows per level (cum) and per-plane counts
__constant__ int c_bEnd[5]  = {12864,19328,22624,24320,25216};
__constant__ int c_bpp[5]   = {804,404,206,106,56};

#define NTILE 1596   // 4 b * 399 strips

// merged prep grid layout — irregular latency-bound jobs FIRST so they hide
// under prep_x's DRAM stream instead of forming the kernel's tail
#define PB_Z   792                   // zero_pad blocks (25344*8/256)
#define PB_W   512                   // prep_w blocks (1 o-channel each, smem transpose)
#define PB_X   25680                 // prep_x blocks
#define PB_ALL (PB_Z + PB_W + PB_X)

__device__ __forceinline__ u32 smem_u32(const void* p){
    u32 a; asm("{ .reg .u64 t; cvta.to.shared.u64 t, %1; cvt.u32.u64 %0, t; }":"=r"(a):"l"(p));
    return a;
}
#define CP_ASYNC16(dst,src) asm volatile("cp.async.cg.shared.global [%0], [%1], 16;"::"r"(dst),"l"(src):"memory")
#define CP_COMMIT()     asm volatile("cp.async.commit_group;":::"memory")
#define CP_WAIT(n)      asm volatile("cp.async.wait_group %0;"::"n"(n):"memory")
#define LDSM_X4(r0,r1,r2,r3,a) asm volatile("ldmatrix.sync.aligned.m8n8.x4.shared.b16 {%0,%1,%2,%3}, [%4];" \
    : "=r"(r0),"=r"(r1),"=r"(r2),"=r"(r3) : "r"(a))
#define MMA16816(c0,c1,c2,c3,a0,a1,a2,a3,b0,b1) \
    asm volatile("mma.sync.aligned.m16n8k16.row.col.f32.f16.f16.f32 {%0,%1,%2,%3},{%4,%5,%6,%7},{%8,%9},{%0,%1,%2,%3};" \
    : "+f"(c0),"+f"(c1),"+f"(c2),"+f"(c3) : "r"(a0),"r"(a1),"r"(a2),"r"(a3),"r"(b0),"r"(b1))

// ---------------- merged prep kernel ----------------
__global__ __launch_bounds__(256)
void prep(const float* p0,const float* p1,const float* p2,const float* p3,const float* p4,
          const float* __restrict__ Wc)
{
    __shared__ __align__(16) char sbuf[4608];
    const int tid = threadIdx.x;
    int bid = blockIdx.x;

    if (bid < PB_Z) {
        // ---- zero border rows + trailing slack ----
        int id = bid*256 + tid;
        if (id >= 25344*8) return;
        int bi = id >> 3, u = id & 7;
        size_t row;
        if (bi >= 25216) {
            row = 825808 + (bi - 25216);
        } else {
            int l = 0; while (bi >= c_bEnd[l]) l++;
            int r = bi - (l ? c_bEnd[l-1] : 0);
            int k = c_bpp[l];
            int plane = r / k, j = r - plane*k;
            int Wp = c_Wp[l], Hp = c_Hp[l], W = c_W[l];
            int hp, wp;
            if (j < 2*Wp) { hp = (j >= Wp) ? (Hp-1) : 0; wp = (j >= Wp) ? (j - Wp) : j; }
            else { int j2 = j - 2*Wp; hp = 1 + (j2 >> 1); wp = (j2 & 1) ? (W+1) : 0; }
            row = (size_t)c_xbase[l] + (size_t)plane*c_plane[l] + (size_t)hp*Wp + wp;
        }
        __stcs((uint4*)((char*)g_x + row*128 + u*16), make_uint4(0,0,0,0));
        return;
    }
    bid -= PB_Z;

    if (bid < PB_W) {
        // ---- prep_w: smem transpose, 1 o-channel per block ----
        __half* sh = (__half*)sbuf;                  // [2304] halfs = 4608 B
        int o = bid;
        for (int i = tid; i < 2304; i += 256)
            sh[i] = __float2half_rn(Wc[(size_t)o*2304 + i]);
        __syncthreads();
        for (int u = tid; u < 288; u += 256) {
            int kb = u >> 3, jq = u & 7;
            int cc = kb & 3, t = kb >> 2;
            __half hv[8];
#pragma unroll
            for (int j = 0; j < 8; j++)
                hv[j] = sh[(cc*64 + jq*8 + j)*9 + t];
            *(uint4*)&g_wb[(size_t)kb*32768 + (size_t)o*64 + jq*8] = *(uint4*)hv;
        }
        return;
    }
    bid -= PB_W;

    // ---- prep_x: NCHW fp32 -> padded NHWC fp16 (interior rows) ----
    {
        __half (*s)[72] = (__half(*)[72])sbuf;   // 144B row stride: conflict-free 128-bit ops
        int l = 0;
        while (bid >= c_pbEnd[l]) l++;
        int r = bid - (l ? c_pbEnd[l-1] : 0);
        int H = c_H[l], W = c_W[l], Wp = c_Wp[l], plane = c_plane[l];
        int wbl = c_wbl[l];
        int wb = r % wbl; int t1 = r / wbl;
        int h = t1 % H;   int bc = t1 / H;
        int b = bc >> 2, cc = bc & 3;
        const float* x = (l==0)?p0:(l==1)?p1:(l==2)?p2:(l==3)?p3:p4;

        {
            // thread handles 8 CONSECUTIVE channels (warp-uniform channel per iter -> coalesced)
            int c0 = tid >> 5, wl = tid & 31;
            int w = wb*32 + wl;
            const float* px = x + ((size_t)(b*256 + cc*64 + c0*8)*H + h)*W + w;
            size_t cs = (size_t)H*W;
            __half2 hv[4];
#pragma unroll
            for (int i = 0; i < 4; i++) {
                float v0 = (w < W) ? __ldcs(px + (2*i)*cs)   : 0.f;
                float v1 = (w < W) ? __ldcs(px + (2*i+1)*cs) : 0.f;
                hv[i] = __floats2half2_rn(v0, v1);
            }
            *(uint4*)&s[wl][c0*8] = *(uint4*)hv;       // single STS.128
        }
        __syncthreads();
        {
            int cu = tid & 7, wl = tid >> 3;
            int w = wb*32 + wl;
            if (w < W) {
                size_t row = (size_t)c_xbase[l] + (size_t)(b*4 + cc)*plane + (size_t)(h+1)*Wp + (w+1);
                uint4 v = *(uint4*)&s[wl][cu*8];       // single LDS.128
                __stcs((uint4*)((char*)g_x + row*128 + cu*16), v);
            }
        }
    }
}

// ---------------- gemm1: conv as implicit GEMM (HMMA) + fused head ----------------
#define STG_STRIDE 32768
#define SMEM_G1    (98304 + 6528)   // 3 stages + W_head [24][136] fp16

__global__ void __launch_bounds__(256, 2)
gemm1(const float* __restrict__ b_conv,
      const float* __restrict__ W_cls, const float* __restrict__ W_box)
{
    extern __shared__ char sm[];
    const u32 sb = smem_u32(sm);
    const int tid = threadIdx.x, lane = tid & 31, warp = tid >> 5;
    const int wm = warp & 1, wn = warp >> 1;
    const int n0 = blockIdx.x << 7;
    const int tile = blockIdx.y;

    // strip decode
    int b = tile / 399; int r = tile - b*399;
    int l = 0; while (r >= c_sEnd[l]) l++;
    int s = r - (l ? c_sEnd[l-1] : 0);
    int Wp = c_Wp[l], plane = c_plane[l];
    size_t abase = (size_t)c_xbase[l] + (size_t)(b*4)*plane + (size_t)s*128;

    u32 dsw[4];
#pragma unroll
    for (int q = 0; q < 4; q++) {
        int u = tid + q*256, row = u >> 3, col = u & 7;
        dsw[q] = row*128 + (col ^ (row & 7))*16;
    }

    float c[4][4][4];
#pragma unroll
    for (int mf=0; mf<4; mf++)
#pragma unroll
        for (int nf=0; nf<4; nf++)
#pragma unroll
            for (int q=0; q<4; q++) c[mf][nf][q] = 0.f;

#define GA_PTR(KB) ((const char*)g_x + (abase + (size_t)((KB) & 3)*plane +            \
        (size_t)((((KB)>>2) >= 6) ? 2 : (((KB)>>2) >= 3) ? 1 : 0)*Wp +                \
        (size_t)(((KB)>>2) - ((((KB)>>2) >= 6) ? 2 : (((KB)>>2) >= 3) ? 1 : 0)*3))*128)
#define GB_PTR(KB) ((const char*)g_wb + ((size_t)(KB)*512 + n0)*128)

#define LOAD_A(KB, SLOT) do {                                                  \
        const char* _gA = GA_PTR(KB);                                          \
        u32 _s = sb + (SLOT)*STG_STRIDE;                                       \
        _Pragma("unroll")                                                      \
        for (int _r = 0; _r < 4; _r++)                                         \
            CP_ASYNC16(_s + dsw[_r], _gA + tid*16 + _r*4096);                  \
    } while (0)
#define LOAD_B(KB, SLOT) do {                                                  \
        const char* _gB = GB_PTR(KB);                                          \
        u32 _s = sb + (SLOT)*STG_STRIDE + 16384;                               \
        _Pragma("unroll")                                                      \
        for (int _r = 0; _r < 4; _r++)                                         \
            CP_ASYNC16(_s + dsw[_r], _gB + tid*16 + _r*4096);                  \
    } while (0)

#define KS_STEP(ST, KS) do {                                                   \
        u32 a[4][4];                                                           \
        _Pragma("unroll")                                                      \
        for (int mf = 0; mf < 4; mf++)                                         \
            LDSM_X4(a[mf][0], a[mf][1], a[mf][2], a[mf][3],                    \
                    (ST) + mf*2048 + offA[KS]);                                \
        u32 bf[4][2];                                                          \
        _Pragma("unroll")                                                      \
        for (int pr = 0; pr < 2; pr++)                                         \
            LDSM_X4(bf[2*pr][0], bf[2*pr][1], bf[2*pr+1][0], bf[2*pr+1][1],    \
                    (ST) + pr*2048 + offB[KS]);                                \
        _Pragma("unroll")                                                      \
        for (int mf = 0; mf < 4; mf++)                                         \
            _Pragma("unroll")                                                  \
            for (int nf = 0; nf < 4; nf++)                                     \
                MMA16816(c[mf][nf][0], c[mf][nf][1], c[mf][nf][2], c[mf][nf][3],\
                         a[mf][0], a[mf][1], a[mf][2], a[mf][3],               \
                         bf[nf][0], bf[nf][1]);                                \
    } while (0)

    // prologue loads FIRST so sWh staging overlaps the DRAM latency
    LOAD_A(0, 0); LOAD_B(0, 0); CP_COMMIT();
    LOAD_A(1, 1); LOAD_B(1, 1); CP_COMMIT();

    // stage head-weight slice: sWh[24][136] fp16 (rows 18..23 zero)
    {
        __half* sWh = (__half*)(sm + 98304);
        for (int i = tid; i < 24*128; i += 256) {
            int j = i >> 7, k = i & 127;
            float v = (j < 6) ? W_cls[j*512 + n0 + k]
                    : (j < 18) ? W_box[(j-6)*512 + n0 + k] : 0.f;
            sWh[j*136 + k] = __float2half_rn(v);
        }
    }

    u32 offA[4], offB[4];
    {
        int rowA = wm*64 + (lane & 15), kA = lane >> 4;
        int rB0  = wn*32 + ((lane >> 4) << 3) + (lane & 7), kB = (lane >> 3) & 1;
#pragma unroll
        for (int ks = 0; ks < 4; ks++) {
            offA[ks] = rowA*128 + ((2*ks + kA) ^ (rowA & 7))*16;
            offB[ks] = rB0*128 + 16384 + ((2*ks + kB) ^ (lane & 7))*16;
        }
    }

    CP_WAIT(1);
    __syncthreads();

#pragma unroll 3
    for (int kb = 0; kb < 36; kb++) {
        const int slot = kb % 3;
        const int nslot = (kb + 2) % 3;
        u32 st = sb + slot*STG_STRIDE;

        KS_STEP(st, 0);
        if (kb + 2 < 36) LOAD_A(kb + 2, nslot);
        KS_STEP(st, 1);
        if (kb + 2 < 36) LOAD_B(kb + 2, nslot);
        CP_COMMIT();
        KS_STEP(st, 2);
        KS_STEP(st, 3);

        CP_WAIT(1);
        __syncthreads();
    }

    // ---- fused epilogue: bias + ReLU -> fp16 tile in smem (slot 0, swizzled) ----
#pragma unroll
    for (int nf = 0; nf < 4; nf++) {
        int chl = wn*32 + nf*8 + (lane & 3)*2;      // 0..127
        int half = chl >> 6, chin = chl & 63;
        float bx = b_conv[n0 + chl], by = b_conv[n0 + chl + 1];
#pragma unroll
        for (int mf = 0; mf < 4; mf++) {
            int pos = wm*64 + mf*16 + (lane >> 2);
            float v0 = c[mf][nf][0] + bx, v1 = c[mf][nf][1] + by;
            float v2 = c[mf][nf][2] + bx, v3 = c[mf][nf][3] + by;
            v0 = v0 > 0.f ? v0 : 0.f;  v1 = v1 > 0.f ? v1 : 0.f;
            v2 = v2 > 0.f ? v2 : 0.f;  v3 = v3 > 0.f ? v3 : 0.f;
            __half2 h01 = __floats2half2_rn(v0, v1);
            __half2 h23 = __floats2half2_rn(v2, v3);
            u32 a0 = (u32)((half*128 + pos)*128     + (((chin>>3) ^ (pos & 7)))*16     + (chin & 7)*2);
            u32 a1 = (u32)((half*128 + pos + 8)*128 + (((chin>>3) ^ ((pos+8) & 7)))*16 + (chin & 7)*2);
            *(u32*)(sm + a0) = *(u32*)&h01;
            *(u32*)(sm + a1) = *(u32*)&h23;
        }
    }
    __syncthreads();

    // ---- head projection: per warp M=16, N=24, K=128 ----
    float c2[3][4];
#pragma unroll
    for (int nf=0; nf<3; nf++)
#pragma unroll
        for (int q=0; q<4; q++) c2[nf][q] = 0.f;

    const char* sWb = sm + 98304;
    {
        int rowA = warp*16 + (lane & 15), kA = lane >> 4;
        int nIdx = lane >> 2, kLo = (lane & 3)*2;
#pragma unroll
        for (int half = 0; half < 2; half++)
#pragma unroll
            for (int ks = 0; ks < 4; ks++) {
                u32 a0,a1,a2,a3;
                LDSM_X4(a0,a1,a2,a3,
                        sb + (half*128 + rowA)*128 + ((2*ks + kA) ^ (rowA & 7))*16);
                int k0 = half*64 + ks*16 + kLo;
#pragma unroll
                for (int nf = 0; nf < 3; nf++) {
                    int n = nf*8 + nIdx;
                    u32 b0 = *(const u32*)(sWb + (n*136 + k0)*2);
                    u32 b1 = *(const u32*)(sWb + (n*136 + k0 + 8)*2);
                    MMA16816(c2[nf][0], c2[nf][1], c2[nf][2], c2[nf][3],
                             a0, a1, a2, a3, b0, b1);
                }
            }
    }

    // ---- store 18-dim partials for this n-slice (stride 20) ----
    {
        float* gp = g_part + (size_t)blockIdx.x*PSLICE + (size_t)tile*128*20;
        int pos0 = warp*16 + (lane >> 2);
        int ncol = (lane & 3)*2;
#pragma unroll
        for (int nf = 0; nf < 3; nf++) {
            int n = nf*8 + ncol;
            if (n < 18) {
                gp[pos0*20 + n]     = c2[nf][0];
                gp[(pos0+8)*20 + n] = c2[nf][2];
            }
            if (n + 1 < 18) {
                gp[pos0*20 + n + 1]     = c2[nf][1];
                gp[(pos0+8)*20 + n + 1] = c2[nf][3];
            }
        }
    }
}

// ---------------- scatter: sum 4 slices + bias + softmax + write (2 tiles/block) ----------------
__global__ __launch_bounds__(256)
void scatter(const float* __restrict__ b_cls, const float* __restrict__ b_box,
             float* __restrict__ out)
{
    const int tid = threadIdx.x & 127;
    const int tile = blockIdx.x*2 + (threadIdx.x >> 7);

    int b = tile / 399; int r = tile - b*399;
    int l = 0; while (r >= c_sEnd[l]) l++;
    int s = r - (l ? c_sEnd[l-1] : 0);
    int W = c_W[l], H = c_H[l], Wp = c_Wp[l];

    int q = Wp + 1 + s*128 + tid;
    int hp = q / Wp, wp = q - hp*Wp;
    if (wp >= 1 && wp <= W && hp <= H) {
        int h = hp - 1, w = wp - 1;
        size_t base = ((size_t)tile*128 + tid)*20;
        float so[20];
#pragma unroll
        for (int qq = 0; qq < 5; qq++) {
            float4 v0 = *(const float4*)&g_part[base + qq*4];
            float4 v1 = *(const float4*)&g_part[PSLICE + base + qq*4];
            float4 v2 = *(const float4*)&g_part[2u*PSLICE + base + qq*4];
            float4 v3 = *(const float4*)&g_part[3u*PSLICE + base + qq*4];
            so[qq*4+0] = v0.x + v1.x + v2.x + v3.x;
            so[qq*4+1] = v0.y + v1.y + v2.y + v3.y;
            so[qq*4+2] = v0.z + v1.z + v2.z + v3.z;
            so[qq*4+3] = v0.w + v1.w + v2.w + v3.w;
        }
#pragma unroll
        for (int j = 0; j < 18; j++)
            so[j] += (j < 6 ? b_cls[j] : b_box[j-6]);
        int rowo = c_rowBase[l] + (h*W + w)*3;
        float* pout = out + (size_t)2*NB*ATOT;
        float* bout = out + (size_t)4*NB*ATOT;
#pragma unroll
        for (int a = 0; a < 3; a++) {
            int row = rowo + a;
            int base2 = (b*ATOT + row)*2;
            out[base2]   = so[2*a];
            out[base2+1] = so[2*a+1];
#pragma unroll
            for (int k = 0; k < 2; k++) {
                int c2 = 2*a + k, rr = c2 % 3;
                float u0 = so[rr], v0 = so[rr+3];
                float m  = fmaxf(u0, v0);
                float eu = __expf(u0 - m), ev = __expf(v0 - m);
                pout[base2+k] = ((c2 < 3) ? eu : ev) / (eu + ev);
            }
            int base4 = (b*ATOT + row)*4;
#pragma unroll
            for (int j = 0; j < 4; j++) bout[base4+j] = so[6 + 4*a + j];
        }
    }
}

extern "C" void kernel_launch(void* const* d_in, const int* in_sizes, int n_in,
                              void* d_out, int out_size) {
    const float* f[5]; for (int i = 0; i < 5; i++) f[i] = (const float*)d_in[i];
    const float* W_conv = (const float*)d_in[6];
    const float* b_conv = (const float*)d_in[7];
    const float* W_cls  = (const float*)d_in[8];
    const float* b_cls  = (const float*)d_in[9];
    const float* W_box  = (const float*)d_in[10];
    const float* b_box  = (const float*)d_in[11];
    float* out = (float*)d_out;

    cudaFuncSetAttribute(gemm1, cudaFuncAttributeMaxDynamicSharedMemorySize, SMEM_G1);

    prep<<<PB_ALL, 256>>>(f[0], f[1], f[2], f[3], f[4], W_conv);
    gemm1<<<dim3(4, NTILE), 256, SMEM_G1>>>(b_conv, W_cls, W_box);
    scatter<<<NTILE/2, 256>>>(b_cls, b_box, out);
}